// round 1
// baseline (speedup 1.0000x reference)
#include <cuda_runtime.h>
#include <math.h>

#define B_  8
#define S_  1024
#define D_  1024
#define H_  16
#define HD_ 64
#define O3_ 3072
#define BQ  64
#define BK  64

// Scratch (allocation-free): qkv buffer [B*S][3*H*hd] and lora intermediate [B*S][4]
__device__ float g_qkv[(size_t)B_ * S_ * O3_];
__device__ float g_lo[(size_t)B_ * S_ * 4];

// ---------------------------------------------------------------------------
// Kernel 1: lo[b,s,r] = sum_d hs[b,s,d] * lora_A[adapter[b], r, d]
// ---------------------------------------------------------------------------
__global__ void lora_lo_kernel(const float* __restrict__ hs,
                               const float* __restrict__ loraA,
                               const int*   __restrict__ amask) {
    int ms = blockIdx.x;            // b*S + s
    int b  = ms >> 10;
    int a  = amask[b];
    const float* hrow = hs    + (size_t)ms * D_;
    const float* Arow = loraA + (size_t)a * 4 * D_;
    float acc[4] = {0.f, 0.f, 0.f, 0.f};
    for (int d = threadIdx.x; d < D_; d += 128) {
        float hv = hrow[d];
#pragma unroll
        for (int r = 0; r < 4; r++) acc[r] += hv * Arow[r * D_ + d];
    }
#pragma unroll
    for (int r = 0; r < 4; r++)
#pragma unroll
        for (int off = 16; off; off >>= 1)
            acc[r] += __shfl_xor_sync(0xffffffffu, acc[r], off);
    __shared__ float red[4][4];
    int w = threadIdx.x >> 5, lane = threadIdx.x & 31;
    if (lane == 0) {
#pragma unroll
        for (int r = 0; r < 4; r++) red[w][r] = acc[r];
    }
    __syncthreads();
    if (threadIdx.x < 4) {
        int r = threadIdx.x;
        g_lo[(size_t)ms * 4 + r] = red[0][r] + red[1][r] + red[2][r] + red[3][r];
    }
}

// ---------------------------------------------------------------------------
// Kernel 2: qkv[m, o] = hs[m,:]·W[o,:] + bias[o] + 0.25 * lo[m,:]·loraB[a,o,:]
// Tiled fp32 GEMM: BM=64, BN=64, BK=16, 256 threads, 4x4 microtile
// ---------------------------------------------------------------------------
__global__ void qkv_gemm_kernel(const float* __restrict__ hs,
                                const float* __restrict__ W,
                                const float* __restrict__ bias,
                                const float* __restrict__ loraB,
                                const int*   __restrict__ amask) {
    __shared__ __align__(16) float As[16][64];
    __shared__ __align__(16) float Bs[16][64];
    int tid = threadIdx.x;
    int m0 = blockIdx.y * 64, n0 = blockIdx.x * 64;
    int tm = tid & 15, tn = tid >> 4;
    int lrow = tid >> 2, lk = (tid & 3) * 4;

    float acc[4][4];
#pragma unroll
    for (int i = 0; i < 4; i++)
#pragma unroll
        for (int j = 0; j < 4; j++) acc[i][j] = 0.f;

    const float* gA = hs + (size_t)(m0 + lrow) * D_ + lk;
    const float* gB = W  + (size_t)(n0 + lrow) * D_ + lk;

    for (int k0 = 0; k0 < D_; k0 += 16) {
        float4 av = *(const float4*)(gA + k0);
        float4 bv = *(const float4*)(gB + k0);
        __syncthreads();
        As[lk + 0][lrow] = av.x; As[lk + 1][lrow] = av.y;
        As[lk + 2][lrow] = av.z; As[lk + 3][lrow] = av.w;
        Bs[lk + 0][lrow] = bv.x; Bs[lk + 1][lrow] = bv.y;
        Bs[lk + 2][lrow] = bv.z; Bs[lk + 3][lrow] = bv.w;
        __syncthreads();
#pragma unroll
        for (int kk = 0; kk < 16; kk++) {
            float4 a4 = *(const float4*)&As[kk][tm * 4];
            float4 b4 = *(const float4*)&Bs[kk][tn * 4];
            float av4[4] = {a4.x, a4.y, a4.z, a4.w};
            float bv4[4] = {b4.x, b4.y, b4.z, b4.w};
#pragma unroll
            for (int i = 0; i < 4; i++)
#pragma unroll
                for (int j = 0; j < 4; j++) acc[i][j] += av4[i] * bv4[j];
        }
    }

    // Epilogue: bias + rank-4 LoRA delta
    int a = amask[m0 >> 10];
    float4 lv[4], Bv[4];
    float bs4[4];
#pragma unroll
    for (int i = 0; i < 4; i++)
        lv[i] = *(const float4*)&g_lo[(size_t)(m0 + tm * 4 + i) * 4];
#pragma unroll
    for (int j = 0; j < 4; j++) {
        int n = n0 + tn * 4 + j;
        Bv[j]  = *(const float4*)&loraB[((size_t)a * O3_ + n) * 4];
        bs4[j] = bias[n];
    }
#pragma unroll
    for (int i = 0; i < 4; i++) {
        int m = m0 + tm * 4 + i;
#pragma unroll
        for (int j = 0; j < 4; j++) {
            int n = n0 + tn * 4 + j;
            float delta = lv[i].x * Bv[j].x + lv[i].y * Bv[j].y +
                          lv[i].z * Bv[j].z + lv[i].w * Bv[j].w;
            g_qkv[(size_t)m * O3_ + n] = acc[i][j] + bs4[j] + 0.25f * delta;
        }
    }
}

// ---------------------------------------------------------------------------
// Kernel 3: RoPE on q,k in-place; fold hd^-0.5 = 0.125 into q
// thread -> (b*S+s, t in {0,1}, h, i in 0..31) handles the pair (i, i+32)
// ---------------------------------------------------------------------------
__global__ void rope_kernel(const float* __restrict__ cosb,
                            const float* __restrict__ sinb) {
    int idx = blockIdx.x * blockDim.x + threadIdx.x;  // B*S*2*H*32
    int i  = idx & 31;
    int h  = (idx >> 5) & 15;
    int t  = (idx >> 9) & 1;
    int bs = idx >> 10;
    size_t base = ((size_t)bs * 3 + t) * 1024 + h * 64;
    float x1 = g_qkv[base + i], x2 = g_qkv[base + i + 32];
    size_t cb = (size_t)bs * 64;
    float c1 = cosb[cb + i], c2 = cosb[cb + i + 32];
    float s1 = sinb[cb + i], s2 = sinb[cb + i + 32];
    float n1 = x1 * c1 - x2 * s1;
    float n2 = x2 * c2 + x1 * s2;
    if (t == 0) { n1 *= 0.125f; n2 *= 0.125f; }
    g_qkv[base + i]      = n1;
    g_qkv[base + i + 32] = n2;
}

// ---------------------------------------------------------------------------
// Kernel 4: flash attention. 1 block per (q-tile 64, h, b). 256 threads.
// Thread (qi = tid/4, qq = tid%4) owns O[qi][qq*16 .. +15].
// ---------------------------------------------------------------------------
extern __shared__ float sm_attn[];

__global__ void attn_kernel(const float* __restrict__ mask,
                            float* __restrict__ out) {
    float* Qs   = sm_attn;            // 4096
    float* Ks   = sm_attn + 4096;     // 4096
    float* Vs   = sm_attn + 8192;     // 4096
    float* Ps   = sm_attn + 12288;    // 4096
    float* Msk  = sm_attn + 16384;    // 64
    float* redm = sm_attn + 16448;    // 256
    float* reds = sm_attn + 16704;    // 256

    int q0 = blockIdx.x * BQ;
    int h  = blockIdx.y;
    int b  = blockIdx.z;
    int tid = threadIdx.x;
    int qi = tid >> 2, qq = tid & 3;

    // Load Q tile (t=0 slot, q already scaled by 0.125 in RoPE)
    {
        int r = tid >> 2, c0 = (tid & 3) * 16;
        const float* gq = g_qkv + ((size_t)(b * S_ + q0 + r) * 3 + 0) * 1024 + h * 64 + c0;
#pragma unroll
        for (int i = 0; i < 4; i++)
            *(float4*)&Qs[r * 64 + c0 + i * 4] = *(const float4*)(gq + i * 4);
    }

    float O[16];
#pragma unroll
    for (int i = 0; i < 16; i++) O[i] = 0.f;
    float m = -1e30f, l = 0.f;

    for (int k0 = 0; k0 < S_; k0 += BK) {
        __syncthreads();  // protect Ks/Vs/Ps/red from previous iteration readers
        {
            int r = tid >> 2, c0 = (tid & 3) * 16;
            const float* gk = g_qkv + ((size_t)(b * S_ + k0 + r) * 3 + 1) * 1024 + h * 64 + c0;
            const float* gv = g_qkv + ((size_t)(b * S_ + k0 + r) * 3 + 2) * 1024 + h * 64 + c0;
#pragma unroll
            for (int i = 0; i < 4; i++) {
                *(float4*)&Ks[r * 64 + c0 + i * 4] = *(const float4*)(gk + i * 4);
                *(float4*)&Vs[r * 64 + c0 + i * 4] = *(const float4*)(gv + i * 4);
            }
            if (tid < 64) Msk[tid] = mask[(size_t)b * S_ + k0 + tid];
        }
        __syncthreads();

        // Scores: s[jj] for j = qq*16 + jj
        float s[16];
#pragma unroll
        for (int jj = 0; jj < 16; jj++) s[jj] = 0.f;
#pragma unroll 4
        for (int d4 = 0; d4 < 16; d4++) {
            float4 qv = *(const float4*)&Qs[qi * 64 + d4 * 4];
#pragma unroll
            for (int jj = 0; jj < 16; jj++) {
                float4 kv = *(const float4*)&Ks[(qq * 16 + jj) * 64 + d4 * 4];
                s[jj] += qv.x * kv.x + qv.y * kv.y + qv.z * kv.z + qv.w * kv.w;
            }
        }
        float tmax = -1e30f;
#pragma unroll
        for (int jj = 0; jj < 16; jj++) {
            s[jj] += Msk[qq * 16 + jj];
            tmax = fmaxf(tmax, s[jj]);
        }
        redm[qi * 4 + qq] = tmax;
        __syncthreads();
        float mt = fmaxf(fmaxf(redm[qi * 4 + 0], redm[qi * 4 + 1]),
                         fmaxf(redm[qi * 4 + 2], redm[qi * 4 + 3]));
        float mn = fmaxf(m, mt);
        float scale = __expf(m - mn);
        float tsum = 0.f;
#pragma unroll
        for (int jj = 0; jj < 16; jj++) {
            float p = __expf(s[jj] - mn);
            Ps[qi * 64 + qq * 16 + jj] = p;
            tsum += p;
        }
        reds[qi * 4 + qq] = tsum;
        m = mn;
        __syncthreads();
        l = l * scale + reds[qi * 4 + 0] + reds[qi * 4 + 1] +
                        reds[qi * 4 + 2] + reds[qi * 4 + 3];
#pragma unroll
        for (int i = 0; i < 16; i++) O[i] *= scale;
#pragma unroll 8
        for (int j = 0; j < 64; j++) {
            float p = Ps[qi * 64 + j];
#pragma unroll
            for (int d4 = 0; d4 < 4; d4++) {
                float4 vv = *(const float4*)&Vs[j * 64 + qq * 16 + d4 * 4];
                O[d4 * 4 + 0] += p * vv.x;
                O[d4 * 4 + 1] += p * vv.y;
                O[d4 * 4 + 2] += p * vv.z;
                O[d4 * 4 + 3] += p * vv.w;
            }
        }
    }

    float rinv = 1.f / l;
    float* go = out + (size_t)(b * S_ + q0 + qi) * 1024 + h * 64 + qq * 16;
#pragma unroll
    for (int i = 0; i < 16; i++) go[i] = O[i] * rinv;
}

// ---------------------------------------------------------------------------
extern "C" void kernel_launch(void* const* d_in, const int* in_sizes, int n_in,
                              void* d_out, int out_size) {
    const float* hs    = (const float*)d_in[0];
    const float* mask  = (const float*)d_in[1];
    const float* cosb  = (const float*)d_in[2];
    const float* sinb  = (const float*)d_in[3];
    const int*   amask = (const int*)d_in[4];
    const float* W     = (const float*)d_in[5];
    const float* bias  = (const float*)d_in[6];
    const float* loraA = (const float*)d_in[7];
    const float* loraB = (const float*)d_in[8];
    float* out = (float*)d_out;

    (void)in_sizes; (void)n_in; (void)out_size;

    const int ATTN_SMEM = 16960 * 4;  // 67840 bytes
    cudaFuncSetAttribute(attn_kernel,
                         cudaFuncAttributeMaxDynamicSharedMemorySize, ATTN_SMEM);

    lora_lo_kernel<<<B_ * S_, 128>>>(hs, loraA, amask);

    dim3 g2(O3_ / 64, (B_ * S_) / 64);
    qkv_gemm_kernel<<<g2, 256>>>(hs, W, bias, loraB, amask);

    rope_kernel<<<(B_ * S_ * 2 * H_ * 32) / 256, 256>>>(cosb, sinb);

    dim3 g4(S_ / BQ, H_, B_);
    attn_kernel<<<g4, 256, ATTN_SMEM>>>(mask, out);
}

// round 2
// speedup vs baseline: 3.6069x; 3.6069x over previous
#include <cuda_runtime.h>
#include <math.h>

#define B_  8
#define S_  1024
#define D_  1024
#define H_  16
#define O3_ 3072

__device__ float g_qkv[(size_t)B_ * S_ * O3_];
__device__ float g_lo[(size_t)B_ * S_ * 4];

// ---------------------------------------------------------------------------
// Kernel 1: lo[b,s,r] = sum_d hs[b,s,d] * lora_A[adapter[b], r, d]
// ---------------------------------------------------------------------------
__global__ void lora_lo_kernel(const float* __restrict__ hs,
                               const float* __restrict__ loraA,
                               const int*   __restrict__ amask) {
    int ms = blockIdx.x;
    int b  = ms >> 10;
    int a  = amask[b];
    const float* hrow = hs    + (size_t)ms * D_;
    const float* Arow = loraA + (size_t)a * 4 * D_;
    float acc[4] = {0.f, 0.f, 0.f, 0.f};
    for (int d = threadIdx.x * 4; d < D_; d += 128 * 4) {
        float4 hv = *(const float4*)(hrow + d);
#pragma unroll
        for (int r = 0; r < 4; r++) {
            float4 av = *(const float4*)(Arow + r * D_ + d);
            acc[r] += hv.x * av.x + hv.y * av.y + hv.z * av.z + hv.w * av.w;
        }
    }
#pragma unroll
    for (int r = 0; r < 4; r++)
#pragma unroll
        for (int off = 16; off; off >>= 1)
            acc[r] += __shfl_xor_sync(0xffffffffu, acc[r], off);
    __shared__ float red[4][4];
    int w = threadIdx.x >> 5, lane = threadIdx.x & 31;
    if (lane == 0) {
#pragma unroll
        for (int r = 0; r < 4; r++) red[w][r] = acc[r];
    }
    __syncthreads();
    if (threadIdx.x < 4) {
        int r = threadIdx.x;
        g_lo[(size_t)ms * 4 + r] = red[0][r] + red[1][r] + red[2][r] + red[3][r];
    }
}

// ---------------------------------------------------------------------------
// Kernel 2: QKV GEMM 128x128x8, 256 threads, 8x8 microtile, double-buffered.
// Thread tile: rows m0+ty*8..+7 ; cols {n0+tx*4..+3} and {n0+64+tx*4..+3}
// ---------------------------------------------------------------------------
__global__ __launch_bounds__(256) void qkv_gemm_kernel(
        const float* __restrict__ hs,
        const float* __restrict__ W,
        const float* __restrict__ bias,
        const float* __restrict__ loraB,
        const int*   __restrict__ amask) {
    __shared__ __align__(16) float As[2][8][132];
    __shared__ __align__(16) float Bs[2][8][132];

    int tid = threadIdx.x;
    int tx = tid & 15, ty = tid >> 4;
    int m0 = blockIdx.y * 128, n0 = blockIdx.x * 128;
    int ar = tid >> 1, ac = (tid & 1) * 4;

    const float* gA = hs + (size_t)(m0 + ar) * D_ + ac;
    const float* gB = W  + (size_t)(n0 + ar) * D_ + ac;

    float4 a_reg = *(const float4*)gA;
    float4 b_reg = *(const float4*)gB;
    {
        float av[4] = {a_reg.x, a_reg.y, a_reg.z, a_reg.w};
        float bv[4] = {b_reg.x, b_reg.y, b_reg.z, b_reg.w};
#pragma unroll
        for (int i = 0; i < 4; i++) {
            As[0][ac + i][ar] = av[i];
            Bs[0][ac + i][ar] = bv[i];
        }
    }
    __syncthreads();

    float acc[8][8];
#pragma unroll
    for (int i = 0; i < 8; i++)
#pragma unroll
        for (int j = 0; j < 8; j++) acc[i][j] = 0.f;

    const int NK = D_ / 8;
    for (int kt = 0; kt < NK; kt++) {
        int cur = kt & 1;
        if (kt + 1 < NK) {
            a_reg = *(const float4*)(gA + (kt + 1) * 8);
            b_reg = *(const float4*)(gB + (kt + 1) * 8);
        }
#pragma unroll
        for (int kk = 0; kk < 8; kk++) {
            float4 a0 = *(const float4*)&As[cur][kk][ty * 8];
            float4 a1 = *(const float4*)&As[cur][kk][ty * 8 + 4];
            float4 b0 = *(const float4*)&Bs[cur][kk][tx * 4];
            float4 b1 = *(const float4*)&Bs[cur][kk][64 + tx * 4];
            float a[8] = {a0.x, a0.y, a0.z, a0.w, a1.x, a1.y, a1.z, a1.w};
            float b[8] = {b0.x, b0.y, b0.z, b0.w, b1.x, b1.y, b1.z, b1.w};
#pragma unroll
            for (int i = 0; i < 8; i++)
#pragma unroll
                for (int j = 0; j < 8; j++) acc[i][j] += a[i] * b[j];
        }
        if (kt + 1 < NK) {
            int nxt = cur ^ 1;
            float av[4] = {a_reg.x, a_reg.y, a_reg.z, a_reg.w};
            float bv[4] = {b_reg.x, b_reg.y, b_reg.z, b_reg.w};
#pragma unroll
            for (int i = 0; i < 4; i++) {
                As[nxt][ac + i][ar] = av[i];
                Bs[nxt][ac + i][ar] = bv[i];
            }
            __syncthreads();
        }
    }

    // Epilogue: bias + rank-4 LoRA delta
    int a_idx = amask[m0 >> 10];
    float4 Bv[2][4];
    float  bb[2][4];
#pragma unroll
    for (int jg = 0; jg < 2; jg++)
#pragma unroll
        for (int j = 0; j < 4; j++) {
            int n = n0 + jg * 64 + tx * 4 + j;
            Bv[jg][j] = *(const float4*)&loraB[((size_t)a_idx * O3_ + n) * 4];
            bb[jg][j] = bias[n];
        }
#pragma unroll
    for (int i = 0; i < 8; i++) {
        int m = m0 + ty * 8 + i;
        float4 lv = *(const float4*)&g_lo[(size_t)m * 4];
#pragma unroll
        for (int jg = 0; jg < 2; jg++) {
            float o[4];
#pragma unroll
            for (int j = 0; j < 4; j++) {
                float delta = lv.x * Bv[jg][j].x + lv.y * Bv[jg][j].y +
                              lv.z * Bv[jg][j].z + lv.w * Bv[jg][j].w;
                o[j] = acc[i][jg * 4 + j] + bb[jg][j] + 0.25f * delta;
            }
            *(float4*)&g_qkv[(size_t)m * O3_ + n0 + jg * 64 + tx * 4] =
                make_float4(o[0], o[1], o[2], o[3]);
        }
    }
}

// ---------------------------------------------------------------------------
// Kernel 3: RoPE on q,k in-place; fold hd^-0.5 = 0.125 into q
// ---------------------------------------------------------------------------
__global__ void rope_kernel(const float* __restrict__ cosb,
                            const float* __restrict__ sinb) {
    int idx = blockIdx.x * blockDim.x + threadIdx.x;
    int i  = idx & 31;
    int h  = (idx >> 5) & 15;
    int t  = (idx >> 9) & 1;
    int bs = idx >> 10;
    size_t base = ((size_t)bs * 3 + t) * 1024 + h * 64;
    float x1 = g_qkv[base + i], x2 = g_qkv[base + i + 32];
    size_t cb = (size_t)bs * 64;
    float c1 = cosb[cb + i], c2 = cosb[cb + i + 32];
    float s1 = sinb[cb + i], s2 = sinb[cb + i + 32];
    float n1 = x1 * c1 - x2 * s1;
    float n2 = x2 * c2 + x1 * s2;
    if (t == 0) { n1 *= 0.125f; n2 *= 0.125f; }
    g_qkv[base + i]      = n1;
    g_qkv[base + i + 32] = n2;
}

// ---------------------------------------------------------------------------
// Kernel 4: flash attention, GEMM-style 4x4 microtiles, conflict-free smem.
// 256 threads as 16x16: tx = n/d columns, ty = q rows.
// Smem (floats, stride 68): Qt[64][68] (Q^T), Kt[64][68] (K^T),
//                           Vs[64][68] (row-major), Pt[64][68] (P^T), Msk[64]
// ---------------------------------------------------------------------------
#define AT_QT 0
#define AT_KT 4352
#define AT_VS 8704
#define AT_PT 13056
#define AT_MS 17408
#define AT_FLOATS 17472

extern __shared__ float sm_attn[];

__global__ __launch_bounds__(256) void attn_kernel(const float* __restrict__ mask,
                                                   float* __restrict__ out) {
    int q0 = blockIdx.x * 64;
    int h  = blockIdx.y;
    int b  = blockIdx.z;
    int tid = threadIdx.x;
    int tx = tid & 15, ty = tid >> 4;

    // Load Q tile transposed (q already roped & scaled by 0.125)
    {
        int r = tid >> 2, c0 = (tid & 3) * 16;
        const float* gq = g_qkv + ((size_t)(b * S_ + q0 + r) * 3 + 0) * 1024 + h * 64 + c0;
        float v[16];
#pragma unroll
        for (int i = 0; i < 4; i++) {
            float4 t = *(const float4*)(gq + i * 4);
            v[i * 4 + 0] = t.x; v[i * 4 + 1] = t.y; v[i * 4 + 2] = t.z; v[i * 4 + 3] = t.w;
        }
#pragma unroll
        for (int ii = 0; ii < 16; ii++)
            sm_attn[AT_QT + (c0 + ii) * 68 + r] = v[ii];
    }

    float O[4][4];
#pragma unroll
    for (int i = 0; i < 4; i++)
#pragma unroll
        for (int j = 0; j < 4; j++) O[i][j] = 0.f;
    float mrow[4] = {-1e30f, -1e30f, -1e30f, -1e30f};
    float lrow[4] = {0.f, 0.f, 0.f, 0.f};

    for (int k0 = 0; k0 < S_; k0 += 64) {
        __syncthreads();  // prior tile fully consumed
        {
            int r = tid >> 2, c0 = (tid & 3) * 16;
            const float* gk = g_qkv + ((size_t)(b * S_ + k0 + r) * 3 + 1) * 1024 + h * 64 + c0;
            const float* gv = g_qkv + ((size_t)(b * S_ + k0 + r) * 3 + 2) * 1024 + h * 64 + c0;
            float kv[16];
#pragma unroll
            for (int i = 0; i < 4; i++) {
                float4 t = *(const float4*)(gk + i * 4);
                kv[i * 4 + 0] = t.x; kv[i * 4 + 1] = t.y; kv[i * 4 + 2] = t.z; kv[i * 4 + 3] = t.w;
                *(float4*)&sm_attn[AT_VS + r * 68 + c0 + i * 4] = *(const float4*)(gv + i * 4);
            }
#pragma unroll
            for (int ii = 0; ii < 16; ii++)
                sm_attn[AT_KT + (c0 + ii) * 68 + r] = kv[ii];
            if (tid < 64) sm_attn[AT_MS + tid] = mask[(size_t)b * S_ + k0 + tid];
        }
        __syncthreads();

        // Scores s[i][j]: rows ty*4+i, cols tx*4+j
        float s[4][4];
#pragma unroll
        for (int i = 0; i < 4; i++)
#pragma unroll
            for (int j = 0; j < 4; j++) s[i][j] = 0.f;
#pragma unroll 8
        for (int kk = 0; kk < 64; kk++) {
            float4 aq = *(const float4*)&sm_attn[AT_QT + kk * 68 + ty * 4];
            float4 bk = *(const float4*)&sm_attn[AT_KT + kk * 68 + tx * 4];
            float a[4] = {aq.x, aq.y, aq.z, aq.w};
            float bb[4] = {bk.x, bk.y, bk.z, bk.w};
#pragma unroll
            for (int i = 0; i < 4; i++)
#pragma unroll
                for (int j = 0; j < 4; j++) s[i][j] += a[i] * bb[j];
        }

        float mk[4];
#pragma unroll
        for (int j = 0; j < 4; j++) mk[j] = sm_attn[AT_MS + tx * 4 + j];

        // Online softmax: row state in registers, butterfly over 16-lane group
        float scl[4];
#pragma unroll
        for (int i = 0; i < 4; i++) {
            float rm = -1e30f;
#pragma unroll
            for (int j = 0; j < 4; j++) {
                s[i][j] += mk[j];
                rm = fmaxf(rm, s[i][j]);
            }
#pragma unroll
            for (int off = 8; off; off >>= 1)
                rm = fmaxf(rm, __shfl_xor_sync(0xffffffffu, rm, off));
            float mn = fmaxf(mrow[i], rm);
            scl[i] = __expf(mrow[i] - mn);
            mrow[i] = mn;
            float rs = 0.f;
#pragma unroll
            for (int j = 0; j < 4; j++) {
                float p = __expf(s[i][j] - mn);
                s[i][j] = p;
                rs += p;
            }
#pragma unroll
            for (int off = 8; off; off >>= 1)
                rs += __shfl_xor_sync(0xffffffffu, rs, off);
            lrow[i] = lrow[i] * scl[i] + rs;
#pragma unroll
            for (int j = 0; j < 4; j++) O[i][j] *= scl[i];
        }

        // Write P transposed: Pt[n][m]
#pragma unroll
        for (int j = 0; j < 4; j++)
#pragma unroll
            for (int i = 0; i < 4; i++)
                sm_attn[AT_PT + (tx * 4 + j) * 68 + ty * 4 + i] = s[i][j];
        __syncthreads();

        // O += P @ V : rows ty*4+i, dcols tx*4+j
#pragma unroll 8
        for (int kk = 0; kk < 64; kk++) {
            float4 ap = *(const float4*)&sm_attn[AT_PT + kk * 68 + ty * 4];
            float4 bv = *(const float4*)&sm_attn[AT_VS + kk * 68 + tx * 4];
            float a[4] = {ap.x, ap.y, ap.z, ap.w};
            float v[4] = {bv.x, bv.y, bv.z, bv.w};
#pragma unroll
            for (int i = 0; i < 4; i++)
#pragma unroll
                for (int j = 0; j < 4; j++) O[i][j] += a[i] * v[j];
        }
    }

#pragma unroll
    for (int i = 0; i < 4; i++) {
        float rinv = 1.f / lrow[i];
        float* go = out + (size_t)(b * S_ + q0 + ty * 4 + i) * 1024 + h * 64 + tx * 4;
        *(float4*)go = make_float4(O[i][0] * rinv, O[i][1] * rinv,
                                   O[i][2] * rinv, O[i][3] * rinv);
    }
}

// ---------------------------------------------------------------------------
extern "C" void kernel_launch(void* const* d_in, const int* in_sizes, int n_in,
                              void* d_out, int out_size) {
    const float* hs    = (const float*)d_in[0];
    const float* mask  = (const float*)d_in[1];
    const float* cosb  = (const float*)d_in[2];
    const float* sinb  = (const float*)d_in[3];
    const int*   amask = (const int*)d_in[4];
    const float* W     = (const float*)d_in[5];
    const float* bias  = (const float*)d_in[6];
    const float* loraA = (const float*)d_in[7];
    const float* loraB = (const float*)d_in[8];
    float* out = (float*)d_out;
    (void)in_sizes; (void)n_in; (void)out_size;

    const int ATTN_SMEM = AT_FLOATS * 4;  // 69888 bytes
    cudaFuncSetAttribute(attn_kernel,
                         cudaFuncAttributeMaxDynamicSharedMemorySize, ATTN_SMEM);

    lora_lo_kernel<<<B_ * S_, 128>>>(hs, loraA, amask);

    dim3 g2(O3_ / 128, (B_ * S_) / 128);
    qkv_gemm_kernel<<<g2, 256>>>(hs, W, bias, loraB, amask);

    rope_kernel<<<(B_ * S_ * 2 * H_ * 32) / 256, 256>>>(cosb, sinb);

    dim3 g4(S_ / 64, H_, B_);
    attn_kernel<<<g4, 256, ATTN_SMEM>>>(mask, out);
}

// round 3
// speedup vs baseline: 3.6117x; 1.0013x over previous
#include <cuda_runtime.h>
#include <math.h>

#define B_  8
#define S_  1024
#define D_  1024
#define H_  16
#define O3_ 3072

__device__ float g_qkv[(size_t)B_ * S_ * O3_];
__device__ float g_lo[(size_t)B_ * S_ * 4];

// ---------------------------------------------------------------------------
// Kernel 1: lo[b,s,r] = sum_d hs[b,s,d] * lora_A[adapter[b], r, d]
// ---------------------------------------------------------------------------
__global__ void lora_lo_kernel(const float* __restrict__ hs,
                               const float* __restrict__ loraA,
                               const int*   __restrict__ amask) {
    int ms = blockIdx.x;
    int b  = ms >> 10;
    int a  = amask[b];
    const float* hrow = hs    + (size_t)ms * D_;
    const float* Arow = loraA + (size_t)a * 4 * D_;
    float acc[4] = {0.f, 0.f, 0.f, 0.f};
    for (int d = threadIdx.x * 4; d < D_; d += 128 * 4) {
        float4 hv = *(const float4*)(hrow + d);
#pragma unroll
        for (int r = 0; r < 4; r++) {
            float4 av = *(const float4*)(Arow + r * D_ + d);
            acc[r] += hv.x * av.x + hv.y * av.y + hv.z * av.z + hv.w * av.w;
        }
    }
#pragma unroll
    for (int r = 0; r < 4; r++)
#pragma unroll
        for (int off = 16; off; off >>= 1)
            acc[r] += __shfl_xor_sync(0xffffffffu, acc[r], off);
    __shared__ float red[4][4];
    int w = threadIdx.x >> 5, lane = threadIdx.x & 31;
    if (lane == 0) {
#pragma unroll
        for (int r = 0; r < 4; r++) red[w][r] = acc[r];
    }
    __syncthreads();
    if (threadIdx.x < 4) {
        int r = threadIdx.x;
        g_lo[(size_t)ms * 4 + r] = red[0][r] + red[1][r] + red[2][r] + red[3][r];
    }
}

// ---------------------------------------------------------------------------
// Kernel 2: QKV GEMM 128x128x8, 256 threads, 8x8 microtile, double-buffered.
// Thread tile: rows m0+ty*8..+7 ; cols {n0+tx*4..+3} and {n0+64+tx*4..+3}
// ---------------------------------------------------------------------------
__global__ __launch_bounds__(256) void qkv_gemm_kernel(
        const float* __restrict__ hs,
        const float* __restrict__ W,
        const float* __restrict__ bias,
        const float* __restrict__ loraB,
        const int*   __restrict__ amask) {
    __shared__ __align__(16) float As[2][8][132];
    __shared__ __align__(16) float Bs[2][8][132];

    int tid = threadIdx.x;
    int tx = tid & 15, ty = tid >> 4;
    int m0 = blockIdx.y * 128, n0 = blockIdx.x * 128;
    int ar = tid >> 1, ac = (tid & 1) * 4;

    const float* gA = hs + (size_t)(m0 + ar) * D_ + ac;
    const float* gB = W  + (size_t)(n0 + ar) * D_ + ac;

    float4 a_reg = *(const float4*)gA;
    float4 b_reg = *(const float4*)gB;
    {
        float av[4] = {a_reg.x, a_reg.y, a_reg.z, a_reg.w};
        float bv[4] = {b_reg.x, b_reg.y, b_reg.z, b_reg.w};
#pragma unroll
        for (int i = 0; i < 4; i++) {
            As[0][ac + i][ar] = av[i];
            Bs[0][ac + i][ar] = bv[i];
        }
    }
    __syncthreads();

    float acc[8][8];
#pragma unroll
    for (int i = 0; i < 8; i++)
#pragma unroll
        for (int j = 0; j < 8; j++) acc[i][j] = 0.f;

    const int NK = D_ / 8;
    for (int kt = 0; kt < NK; kt++) {
        int cur = kt & 1;
        if (kt + 1 < NK) {
            a_reg = *(const float4*)(gA + (kt + 1) * 8);
            b_reg = *(const float4*)(gB + (kt + 1) * 8);
        }
#pragma unroll
        for (int kk = 0; kk < 8; kk++) {
            float4 a0 = *(const float4*)&As[cur][kk][ty * 8];
            float4 a1 = *(const float4*)&As[cur][kk][ty * 8 + 4];
            float4 b0 = *(const float4*)&Bs[cur][kk][tx * 4];
            float4 b1 = *(const float4*)&Bs[cur][kk][64 + tx * 4];
            float a[8] = {a0.x, a0.y, a0.z, a0.w, a1.x, a1.y, a1.z, a1.w};
            float b[8] = {b0.x, b0.y, b0.z, b0.w, b1.x, b1.y, b1.z, b1.w};
#pragma unroll
            for (int i = 0; i < 8; i++)
#pragma unroll
                for (int j = 0; j < 8; j++) acc[i][j] += a[i] * b[j];
        }
        if (kt + 1 < NK) {
            int nxt = cur ^ 1;
            float av[4] = {a_reg.x, a_reg.y, a_reg.z, a_reg.w};
            float bv[4] = {b_reg.x, b_reg.y, b_reg.z, b_reg.w};
#pragma unroll
            for (int i = 0; i < 4; i++) {
                As[nxt][ac + i][ar] = av[i];
                Bs[nxt][ac + i][ar] = bv[i];
            }
            __syncthreads();
        }
    }

    // Epilogue: bias + rank-4 LoRA delta
    int a_idx = amask[m0 >> 10];
    float4 Bv[2][4];
    float  bb[2][4];
#pragma unroll
    for (int jg = 0; jg < 2; jg++)
#pragma unroll
        for (int j = 0; j < 4; j++) {
            int n = n0 + jg * 64 + tx * 4 + j;
            Bv[jg][j] = *(const float4*)&loraB[((size_t)a_idx * O3_ + n) * 4];
            bb[jg][j] = bias[n];
        }
#pragma unroll
    for (int i = 0; i < 8; i++) {
        int m = m0 + ty * 8 + i;
        float4 lv = *(const float4*)&g_lo[(size_t)m * 4];
#pragma unroll
        for (int jg = 0; jg < 2; jg++) {
            float o[4];
#pragma unroll
            for (int j = 0; j < 4; j++) {
                float delta = lv.x * Bv[jg][j].x + lv.y * Bv[jg][j].y +
                              lv.z * Bv[jg][j].z + lv.w * Bv[jg][j].w;
                o[j] = acc[i][jg * 4 + j] + bb[jg][j] + 0.25f * delta;
            }
            *(float4*)&g_qkv[(size_t)m * O3_ + n0 + jg * 64 + tx * 4] =
                make_float4(o[0], o[1], o[2], o[3]);
        }
    }
}

// ---------------------------------------------------------------------------
// Kernel 3: RoPE on q,k in-place; fold hd^-0.5 = 0.125 into q
// ---------------------------------------------------------------------------
__global__ void rope_kernel(const float* __restrict__ cosb,
                            const float* __restrict__ sinb) {
    int idx = blockIdx.x * blockDim.x + threadIdx.x;
    int i  = idx & 31;
    int h  = (idx >> 5) & 15;
    int t  = (idx >> 9) & 1;
    int bs = idx >> 10;
    size_t base = ((size_t)bs * 3 + t) * 1024 + h * 64;
    float x1 = g_qkv[base + i], x2 = g_qkv[base + i + 32];
    size_t cb = (size_t)bs * 64;
    float c1 = cosb[cb + i], c2 = cosb[cb + i + 32];
    float s1 = sinb[cb + i], s2 = sinb[cb + i + 32];
    float n1 = x1 * c1 - x2 * s1;
    float n2 = x2 * c2 + x1 * s2;
    if (t == 0) { n1 *= 0.125f; n2 *= 0.125f; }
    g_qkv[base + i]      = n1;
    g_qkv[base + i + 32] = n2;
}

// ---------------------------------------------------------------------------
// Kernel 4: flash attention, GEMM-style 4x4 microtiles, conflict-free smem.
// 256 threads as 16x16: tx = n/d columns, ty = q rows.
// Smem (floats, stride 68): Qt[64][68] (Q^T), Kt[64][68] (K^T),
//                           Vs[64][68] (row-major), Pt[64][68] (P^T), Msk[64]
// ---------------------------------------------------------------------------
#define AT_QT 0
#define AT_KT 4352
#define AT_VS 8704
#define AT_PT 13056
#define AT_MS 17408
#define AT_FLOATS 17472

extern __shared__ float sm_attn[];

__global__ __launch_bounds__(256) void attn_kernel(const float* __restrict__ mask,
                                                   float* __restrict__ out) {
    int q0 = blockIdx.x * 64;
    int h  = blockIdx.y;
    int b  = blockIdx.z;
    int tid = threadIdx.x;
    int tx = tid & 15, ty = tid >> 4;

    // Load Q tile transposed (q already roped & scaled by 0.125)
    {
        int r = tid >> 2, c0 = (tid & 3) * 16;
        const float* gq = g_qkv + ((size_t)(b * S_ + q0 + r) * 3 + 0) * 1024 + h * 64 + c0;
        float v[16];
#pragma unroll
        for (int i = 0; i < 4; i++) {
            float4 t = *(const float4*)(gq + i * 4);
            v[i * 4 + 0] = t.x; v[i * 4 + 1] = t.y; v[i * 4 + 2] = t.z; v[i * 4 + 3] = t.w;
        }
#pragma unroll
        for (int ii = 0; ii < 16; ii++)
            sm_attn[AT_QT + (c0 + ii) * 68 + r] = v[ii];
    }

    float O[4][4];
#pragma unroll
    for (int i = 0; i < 4; i++)
#pragma unroll
        for (int j = 0; j < 4; j++) O[i][j] = 0.f;
    float mrow[4] = {-1e30f, -1e30f, -1e30f, -1e30f};
    float lrow[4] = {0.f, 0.f, 0.f, 0.f};

    for (int k0 = 0; k0 < S_; k0 += 64) {
        __syncthreads();  // prior tile fully consumed
        {
            int r = tid >> 2, c0 = (tid & 3) * 16;
            const float* gk = g_qkv + ((size_t)(b * S_ + k0 + r) * 3 + 1) * 1024 + h * 64 + c0;
            const float* gv = g_qkv + ((size_t)(b * S_ + k0 + r) * 3 + 2) * 1024 + h * 64 + c0;
            float kv[16];
#pragma unroll
            for (int i = 0; i < 4; i++) {
                float4 t = *(const float4*)(gk + i * 4);
                kv[i * 4 + 0] = t.x; kv[i * 4 + 1] = t.y; kv[i * 4 + 2] = t.z; kv[i * 4 + 3] = t.w;
                *(float4*)&sm_attn[AT_VS + r * 68 + c0 + i * 4] = *(const float4*)(gv + i * 4);
            }
#pragma unroll
            for (int ii = 0; ii < 16; ii++)
                sm_attn[AT_KT + (c0 + ii) * 68 + r] = kv[ii];
            if (tid < 64) sm_attn[AT_MS + tid] = mask[(size_t)b * S_ + k0 + tid];
        }
        __syncthreads();

        // Scores s[i][j]: rows ty*4+i, cols tx*4+j
        float s[4][4];
#pragma unroll
        for (int i = 0; i < 4; i++)
#pragma unroll
            for (int j = 0; j < 4; j++) s[i][j] = 0.f;
#pragma unroll 8
        for (int kk = 0; kk < 64; kk++) {
            float4 aq = *(const float4*)&sm_attn[AT_QT + kk * 68 + ty * 4];
            float4 bk = *(const float4*)&sm_attn[AT_KT + kk * 68 + tx * 4];
            float a[4] = {aq.x, aq.y, aq.z, aq.w};
            float bb[4] = {bk.x, bk.y, bk.z, bk.w};
#pragma unroll
            for (int i = 0; i < 4; i++)
#pragma unroll
                for (int j = 0; j < 4; j++) s[i][j] += a[i] * bb[j];
        }

        float mk[4];
#pragma unroll
        for (int j = 0; j < 4; j++) mk[j] = sm_attn[AT_MS + tx * 4 + j];

        // Online softmax: row state in registers, butterfly over 16-lane group
        float scl[4];
#pragma unroll
        for (int i = 0; i < 4; i++) {
            float rm = -1e30f;
#pragma unroll
            for (int j = 0; j < 4; j++) {
                s[i][j] += mk[j];
                rm = fmaxf(rm, s[i][j]);
            }
#pragma unroll
            for (int off = 8; off; off >>= 1)
                rm = fmaxf(rm, __shfl_xor_sync(0xffffffffu, rm, off));
            float mn = fmaxf(mrow[i], rm);
            scl[i] = __expf(mrow[i] - mn);
            mrow[i] = mn;
            float rs = 0.f;
#pragma unroll
            for (int j = 0; j < 4; j++) {
                float p = __expf(s[i][j] - mn);
                s[i][j] = p;
                rs += p;
            }
#pragma unroll
            for (int off = 8; off; off >>= 1)
                rs += __shfl_xor_sync(0xffffffffu, rs, off);
            lrow[i] = lrow[i] * scl[i] + rs;
#pragma unroll
            for (int j = 0; j < 4; j++) O[i][j] *= scl[i];
        }

        // Write P transposed: Pt[n][m]
#pragma unroll
        for (int j = 0; j < 4; j++)
#pragma unroll
            for (int i = 0; i < 4; i++)
                sm_attn[AT_PT + (tx * 4 + j) * 68 + ty * 4 + i] = s[i][j];
        __syncthreads();

        // O += P @ V : rows ty*4+i, dcols tx*4+j
#pragma unroll 8
        for (int kk = 0; kk < 64; kk++) {
            float4 ap = *(const float4*)&sm_attn[AT_PT + kk * 68 + ty * 4];
            float4 bv = *(const float4*)&sm_attn[AT_VS + kk * 68 + tx * 4];
            float a[4] = {ap.x, ap.y, ap.z, ap.w};
            float v[4] = {bv.x, bv.y, bv.z, bv.w};
#pragma unroll
            for (int i = 0; i < 4; i++)
#pragma unroll
                for (int j = 0; j < 4; j++) O[i][j] += a[i] * v[j];
        }
    }

#pragma unroll
    for (int i = 0; i < 4; i++) {
        float rinv = 1.f / lrow[i];
        float* go = out + (size_t)(b * S_ + q0 + ty * 4 + i) * 1024 + h * 64 + tx * 4;
        *(float4*)go = make_float4(O[i][0] * rinv, O[i][1] * rinv,
                                   O[i][2] * rinv, O[i][3] * rinv);
    }
}

// ---------------------------------------------------------------------------
extern "C" void kernel_launch(void* const* d_in, const int* in_sizes, int n_in,
                              void* d_out, int out_size) {
    const float* hs    = (const float*)d_in[0];
    const float* mask  = (const float*)d_in[1];
    const float* cosb  = (const float*)d_in[2];
    const float* sinb  = (const float*)d_in[3];
    const int*   amask = (const int*)d_in[4];
    const float* W     = (const float*)d_in[5];
    const float* bias  = (const float*)d_in[6];
    const float* loraA = (const float*)d_in[7];
    const float* loraB = (const float*)d_in[8];
    float* out = (float*)d_out;
    (void)in_sizes; (void)n_in; (void)out_size;

    const int ATTN_SMEM = AT_FLOATS * 4;  // 69888 bytes
    cudaFuncSetAttribute(attn_kernel,
                         cudaFuncAttributeMaxDynamicSharedMemorySize, ATTN_SMEM);

    lora_lo_kernel<<<B_ * S_, 128>>>(hs, loraA, amask);

    dim3 g2(O3_ / 128, (B_ * S_) / 128);
    qkv_gemm_kernel<<<g2, 256>>>(hs, W, bias, loraB, amask);

    rope_kernel<<<(B_ * S_ * 2 * H_ * 32) / 256, 256>>>(cosb, sinb);

    dim3 g4(S_ / 64, H_, B_);
    attn_kernel<<<g4, 256, ATTN_SMEM>>>(mask, out);
}

// round 4
// speedup vs baseline: 6.7494x; 1.8688x over previous
#include <cuda_runtime.h>
#include <math.h>
#include <stdint.h>

#define B_  8
#define S_  1024
#define D_  1024
#define H_  16
#define O3_ 3072

__device__ float g_qkv[(size_t)B_ * S_ * O3_];
__device__ float g_lo[(size_t)B_ * S_ * 4];
__device__ float g_vt[(size_t)B_ * H_ * 64 * S_];   // V transposed: [b*H+h][d][s]

// ---------------------------------------------------------------------------
// helpers
// ---------------------------------------------------------------------------
__device__ __forceinline__ uint32_t f2tf(float x) {
    uint32_t u;
    asm("cvt.rna.tf32.f32 %0, %1;" : "=r"(u) : "f"(x));
    return u;
}
__device__ __forceinline__ void ldsm4(uint32_t addr, uint32_t& r0, uint32_t& r1,
                                      uint32_t& r2, uint32_t& r3) {
    asm volatile("ldmatrix.sync.aligned.m8n8.x4.shared.b16 {%0,%1,%2,%3}, [%4];"
                 : "=r"(r0), "=r"(r1), "=r"(r2), "=r"(r3) : "r"(addr));
}
__device__ __forceinline__ void mma8(float c[4], uint32_t a0, uint32_t a1,
                                     uint32_t a2, uint32_t a3,
                                     uint32_t b0, uint32_t b1) {
    asm volatile(
        "mma.sync.aligned.m16n8k8.row.col.f32.tf32.tf32.f32 "
        "{%0,%1,%2,%3},{%4,%5,%6,%7},{%8,%9},{%0,%1,%2,%3};"
        : "+f"(c[0]), "+f"(c[1]), "+f"(c[2]), "+f"(c[3])
        : "r"(a0), "r"(a1), "r"(a2), "r"(a3), "r"(b0), "r"(b1));
}

// ---------------------------------------------------------------------------
// Kernel 1: lo[b,s,r] = sum_d hs[b,s,d] * lora_A[adapter[b], r, d]   (fp32)
// ---------------------------------------------------------------------------
__global__ void lora_lo_kernel(const float* __restrict__ hs,
                               const float* __restrict__ loraA,
                               const int*   __restrict__ amask) {
    int ms = blockIdx.x;
    int b  = ms >> 10;
    int a  = amask[b];
    const float* hrow = hs    + (size_t)ms * D_;
    const float* Arow = loraA + (size_t)a * 4 * D_;
    float acc[4] = {0.f, 0.f, 0.f, 0.f};
    for (int d = threadIdx.x * 4; d < D_; d += 128 * 4) {
        float4 hv = *(const float4*)(hrow + d);
#pragma unroll
        for (int r = 0; r < 4; r++) {
            float4 av = *(const float4*)(Arow + r * D_ + d);
            acc[r] += hv.x * av.x + hv.y * av.y + hv.z * av.z + hv.w * av.w;
        }
    }
#pragma unroll
    for (int r = 0; r < 4; r++)
#pragma unroll
        for (int off = 16; off; off >>= 1)
            acc[r] += __shfl_xor_sync(0xffffffffu, acc[r], off);
    __shared__ float red[4][4];
    int w = threadIdx.x >> 5, lane = threadIdx.x & 31;
    if (lane == 0) {
#pragma unroll
        for (int r = 0; r < 4; r++) red[w][r] = acc[r];
    }
    __syncthreads();
    if (threadIdx.x < 4) {
        int r = threadIdx.x;
        g_lo[(size_t)ms * 4 + r] = red[0][r] + red[1][r] + red[2][r] + red[3][r];
    }
}

// ---------------------------------------------------------------------------
// Kernel 2: QKV GEMM, tf32 mma. Block 128x128, k-step 32, 8 warps (2x4 grid),
// warp tile 64x32. Double-buffered smem (stride 36 words), ldmatrix feeds.
// ---------------------------------------------------------------------------
#define GM_LDA 36
#define GM_BUF 4608   // 128*36 words per buffer

__global__ __launch_bounds__(256) void qkv_gemm_tc(
        const float* __restrict__ hs, const float* __restrict__ W,
        const float* __restrict__ bias, const float* __restrict__ loraB,
        const int* __restrict__ amask) {
    extern __shared__ uint32_t smg[];
    uint32_t* As = smg;                 // [2][GM_BUF]
    uint32_t* Bs = smg + 2 * GM_BUF;    // [2][GM_BUF]
    const int tid  = threadIdx.x;
    const int lane = tid & 31, wid = tid >> 5;
    const int wm = wid & 1, wn = wid >> 1;
    const int m0 = blockIdx.y * 128, n0 = blockIdx.x * 128;

    uint32_t sbase = (uint32_t)__cvta_generic_to_shared(smg);
    uint32_t aB = sbase;
    uint32_t bB = sbase + 2 * GM_BUF * 4;

    const int srow = tid >> 3;          // 0..31
    const int sc4  = (tid & 7) * 4;     // 0..28

    const float* gA = hs + (size_t)m0 * D_;
    const float* gB = W  + (size_t)n0 * D_;

    float4 ar[4], br[4];
#pragma unroll
    for (int i = 0; i < 4; i++) {
        ar[i] = *(const float4*)(gA + (size_t)(srow + i * 32) * D_ + sc4);
        br[i] = *(const float4*)(gB + (size_t)(srow + i * 32) * D_ + sc4);
    }
#pragma unroll
    for (int i = 0; i < 4; i++) {
        int r = srow + i * 32;
        uint4 ua = make_uint4(f2tf(ar[i].x), f2tf(ar[i].y), f2tf(ar[i].z), f2tf(ar[i].w));
        uint4 ub = make_uint4(f2tf(br[i].x), f2tf(br[i].y), f2tf(br[i].z), f2tf(br[i].w));
        *(uint4*)&As[r * GM_LDA + sc4] = ua;
        *(uint4*)&Bs[r * GM_LDA + sc4] = ub;
    }
    __syncthreads();

    float acc[4][4][4];
#pragma unroll
    for (int mi = 0; mi < 4; mi++)
#pragma unroll
        for (int ni = 0; ni < 4; ni++)
#pragma unroll
            for (int c = 0; c < 4; c++) acc[mi][ni][c] = 0.f;

    const int rowAoff = (lane & 7) + ((lane & 16) >> 1);
    const int byteA   = ((lane & 8) >> 3) * 16;
    const int rowBoff = (lane & 7);
    const int byteB   = ((lane >> 3) & 3) * 16;

    const int NKS = D_ / 32;
    for (int ks = 0; ks < NKS; ks++) {
        int buf = ks & 1;
        if (ks + 1 < NKS) {
#pragma unroll
            for (int i = 0; i < 4; i++) {
                ar[i] = *(const float4*)(gA + (size_t)(srow + i * 32) * D_ + (ks + 1) * 32 + sc4);
                br[i] = *(const float4*)(gB + (size_t)(srow + i * 32) * D_ + (ks + 1) * 32 + sc4);
            }
        }
        uint32_t ab = aB + buf * GM_BUF * 4;
        uint32_t bb = bB + buf * GM_BUF * 4;
#pragma unroll
        for (int ktp = 0; ktp < 2; ktp++) {
            uint32_t bf[4][4];
#pragma unroll
            for (int ni = 0; ni < 4; ni++)
                ldsm4(bb + (uint32_t)((wn * 32 + ni * 8 + rowBoff) * GM_LDA) * 4 + ktp * 64 + byteB,
                      bf[ni][0], bf[ni][1], bf[ni][2], bf[ni][3]);
#pragma unroll
            for (int kk = 0; kk < 2; kk++) {
                int kt = ktp * 2 + kk;
                uint32_t a[4][4];
#pragma unroll
                for (int mi = 0; mi < 4; mi++) {
                    uint32_t r0, r1, r2, r3;
                    ldsm4(ab + (uint32_t)((wm * 64 + mi * 16 + rowAoff) * GM_LDA) * 4 + kt * 32 + byteA,
                          r0, r1, r2, r3);
                    a[mi][0] = r0; a[mi][1] = r2; a[mi][2] = r1; a[mi][3] = r3;
                }
#pragma unroll
                for (int mi = 0; mi < 4; mi++)
#pragma unroll
                    for (int ni = 0; ni < 4; ni++)
                        mma8(acc[mi][ni], a[mi][0], a[mi][1], a[mi][2], a[mi][3],
                             bf[ni][kk * 2], bf[ni][kk * 2 + 1]);
            }
        }
        if (ks + 1 < NKS) {
            int nb = buf ^ 1;
            __syncthreads();
            uint32_t* Ad = As + nb * GM_BUF;
            uint32_t* Bd = Bs + nb * GM_BUF;
#pragma unroll
            for (int i = 0; i < 4; i++) {
                int r = srow + i * 32;
                uint4 ua = make_uint4(f2tf(ar[i].x), f2tf(ar[i].y), f2tf(ar[i].z), f2tf(ar[i].w));
                uint4 ub = make_uint4(f2tf(br[i].x), f2tf(br[i].y), f2tf(br[i].z), f2tf(br[i].w));
                *(uint4*)&Ad[r * GM_LDA + sc4] = ua;
                *(uint4*)&Bd[r * GM_LDA + sc4] = ub;
            }
            __syncthreads();
        }
    }

    // epilogue: bias + 0.25 * lo·loraB (fp32)
    const int g = lane >> 2, t = lane & 3;
    int aidx = amask[m0 >> 10];
    float4 loa[4], lob[4];
#pragma unroll
    for (int mi = 0; mi < 4; mi++) {
        int ra = m0 + wm * 64 + mi * 16 + g;
        loa[mi] = *(const float4*)&g_lo[(size_t)ra * 4];
        lob[mi] = *(const float4*)&g_lo[(size_t)(ra + 8) * 4];
    }
#pragma unroll
    for (int ni = 0; ni < 4; ni++) {
        int col = n0 + wn * 32 + ni * 8 + 2 * t;
        float4 LB0 = *(const float4*)&loraB[((size_t)aidx * O3_ + col) * 4];
        float4 LB1 = *(const float4*)&loraB[((size_t)aidx * O3_ + col + 1) * 4];
        float bs0 = bias[col], bs1 = bias[col + 1];
#pragma unroll
        for (int mi = 0; mi < 4; mi++) {
            int ra = m0 + wm * 64 + mi * 16 + g;
            float d00 = acc[mi][ni][0] + bs0 +
                0.25f * (loa[mi].x * LB0.x + loa[mi].y * LB0.y + loa[mi].z * LB0.z + loa[mi].w * LB0.w);
            float d01 = acc[mi][ni][1] + bs1 +
                0.25f * (loa[mi].x * LB1.x + loa[mi].y * LB1.y + loa[mi].z * LB1.z + loa[mi].w * LB1.w);
            float d10 = acc[mi][ni][2] + bs0 +
                0.25f * (lob[mi].x * LB0.x + lob[mi].y * LB0.y + lob[mi].z * LB0.z + lob[mi].w * LB0.w);
            float d11 = acc[mi][ni][3] + bs1 +
                0.25f * (lob[mi].x * LB1.x + lob[mi].y * LB1.y + lob[mi].z * LB1.z + lob[mi].w * LB1.w);
            *(float2*)&g_qkv[(size_t)ra * O3_ + col]       = make_float2(d00, d01);
            *(float2*)&g_qkv[(size_t)(ra + 8) * O3_ + col] = make_float2(d10, d11);
        }
    }
}

// ---------------------------------------------------------------------------
// Kernel 3: RoPE on q,k in-place; fold hd^-0.5 = 0.125 into q
// ---------------------------------------------------------------------------
__global__ void rope_kernel(const float* __restrict__ cosb,
                            const float* __restrict__ sinb) {
    int idx = blockIdx.x * blockDim.x + threadIdx.x;
    int i  = idx & 31;
    int h  = (idx >> 5) & 15;
    int t  = (idx >> 9) & 1;
    int bs = idx >> 10;
    size_t base = ((size_t)bs * 3 + t) * 1024 + h * 64;
    float x1 = g_qkv[base + i], x2 = g_qkv[base + i + 32];
    size_t cb = (size_t)bs * 64;
    float c1 = cosb[cb + i], c2 = cosb[cb + i + 32];
    float s1 = sinb[cb + i], s2 = sinb[cb + i + 32];
    float n1 = x1 * c1 - x2 * s1;
    float n2 = x2 * c2 + x1 * s2;
    if (t == 0) { n1 *= 0.125f; n2 *= 0.125f; }
    g_qkv[base + i]      = n1;
    g_qkv[base + i + 32] = n2;
}

// ---------------------------------------------------------------------------
// Kernel 3b: V transpose -> g_vt[b*H+h][d][s]
// ---------------------------------------------------------------------------
__global__ void vtrans_kernel() {
    __shared__ float t[32][33];
    int b  = blockIdx.z >> 4, h = blockIdx.z & 15;
    int s0 = blockIdx.x * 32, d0 = blockIdx.y * 32;
    int tx = threadIdx.x & 31, ty = threadIdx.x >> 5;
#pragma unroll
    for (int i = 0; i < 4; i++) {
        int s = ty + i * 8;
        t[s][tx] = g_qkv[((size_t)(b * S_ + s0 + s) * 3 + 2) * 1024 + h * 64 + d0 + tx];
    }
    __syncthreads();
#pragma unroll
    for (int i = 0; i < 4; i++) {
        int d = ty + i * 8;
        g_vt[((size_t)(b * H_ + h) * 64 + d0 + d) * S_ + s0 + tx] = t[tx][d];
    }
}

// ---------------------------------------------------------------------------
// Kernel 4: flash attention, tf32 mma. Block = 128 q rows, 8 warps (16 q each).
// Smem words (stride 68): Q[128][68], K[64][68], Vt[64][68], P[128][68], Msk[64]
// ---------------------------------------------------------------------------
#define AT_LDA 68
#define AQ 0
#define AK 8704
#define AV 13056
#define AP 17408
#define AM 26112
#define AT_WORDS 26176

__global__ __launch_bounds__(256) void attn_tc(const float* __restrict__ mask,
                                               float* __restrict__ out) {
    extern __shared__ uint32_t sma[];
    const int tid = threadIdx.x;
    const int lane = tid & 31, w = tid >> 5;
    const int q0 = blockIdx.x * 128;
    const int h  = blockIdx.y;
    const int b  = blockIdx.z;
    const int g = lane >> 2, t = lane & 3;

    uint32_t sbase = (uint32_t)__cvta_generic_to_shared(sma);
    const int rowOffA = (lane & 7) + ((lane & 16) >> 1);  // A-op ldsm row offset
    const int byteA   = ((lane & 8) >> 3) * 16;
    const int rowOffB = (lane & 7);
    const int byteB   = ((lane >> 3) & 3) * 16;

    // Load Q tile (128 x 64), convert to tf32
    for (int idx = tid * 4; idx < 128 * 64; idx += 1024) {
        int r = idx >> 6, c = idx & 63;
        float4 v = *(const float4*)&g_qkv[((size_t)(b * S_ + q0 + r) * 3 + 0) * 1024 + h * 64 + c];
        *(uint4*)&sma[AQ + r * AT_LDA + c] =
            make_uint4(f2tf(v.x), f2tf(v.y), f2tf(v.z), f2tf(v.w));
    }
    __syncthreads();

    // Cache Q fragments: 8 k-steps, A-operand order {r0,r2,r1,r3}
    uint32_t aQ[8][4];
#pragma unroll
    for (int k = 0; k < 8; k++) {
        uint32_t r0, r1, r2, r3;
        ldsm4(sbase + (uint32_t)(AQ + (w * 16 + rowOffA) * AT_LDA) * 4 + k * 32 + byteA,
              r0, r1, r2, r3);
        aQ[k][0] = r0; aQ[k][1] = r2; aQ[k][2] = r1; aQ[k][3] = r3;
    }

    float O[8][4];
#pragma unroll
    for (int ni = 0; ni < 8; ni++)
#pragma unroll
        for (int c = 0; c < 4; c++) O[ni][c] = 0.f;
    float m0r = -1e30f, m1r = -1e30f, l0 = 0.f, l1 = 0.f;

    for (int k0 = 0; k0 < S_; k0 += 64) {
        __syncthreads();
        // K tile (row-major) and Vt tile (d-major), tf32
        for (int idx = tid * 4; idx < 64 * 64; idx += 1024) {
            int r = idx >> 6, c = idx & 63;
            float4 kv = *(const float4*)&g_qkv[((size_t)(b * S_ + k0 + r) * 3 + 1) * 1024 + h * 64 + c];
            *(uint4*)&sma[AK + r * AT_LDA + c] =
                make_uint4(f2tf(kv.x), f2tf(kv.y), f2tf(kv.z), f2tf(kv.w));
            float4 vv = *(const float4*)&g_vt[((size_t)(b * H_ + h) * 64 + r) * S_ + k0 + c];
            *(uint4*)&sma[AV + r * AT_LDA + c] =
                make_uint4(f2tf(vv.x), f2tf(vv.y), f2tf(vv.z), f2tf(vv.w));
        }
        if (tid < 64)
            sma[AM + tid] = __float_as_uint(mask[(size_t)b * S_ + k0 + tid]);
        __syncthreads();

        // S = Q K^T : 8 n-tiles x 8 k-steps
        float s[8][4];
#pragma unroll
        for (int ni = 0; ni < 8; ni++) {
            s[ni][0] = s[ni][1] = s[ni][2] = s[ni][3] = 0.f;
            uint32_t bk[4][4];
#pragma unroll
            for (int ch = 0; ch < 4; ch++)
                ldsm4(sbase + (uint32_t)(AK + (ni * 8 + rowOffB) * AT_LDA) * 4 + ch * 64 + byteB,
                      bk[ch][0], bk[ch][1], bk[ch][2], bk[ch][3]);
#pragma unroll
            for (int k = 0; k < 8; k++)
                mma8(s[ni], aQ[k][0], aQ[k][1], aQ[k][2], aQ[k][3],
                     bk[k >> 1][(k & 1) * 2], bk[k >> 1][(k & 1) * 2 + 1]);
        }

        // mask + online softmax (rows g and g+8 of this warp's 16-row strip)
        float rm0 = -1e30f, rm1 = -1e30f;
#pragma unroll
        for (int ni = 0; ni < 8; ni++) {
            float mk0 = __uint_as_float(sma[AM + ni * 8 + 2 * t]);
            float mk1 = __uint_as_float(sma[AM + ni * 8 + 2 * t + 1]);
            s[ni][0] += mk0; s[ni][1] += mk1;
            s[ni][2] += mk0; s[ni][3] += mk1;
            rm0 = fmaxf(rm0, fmaxf(s[ni][0], s[ni][1]));
            rm1 = fmaxf(rm1, fmaxf(s[ni][2], s[ni][3]));
        }
#pragma unroll
        for (int off = 1; off <= 2; off <<= 1) {
            rm0 = fmaxf(rm0, __shfl_xor_sync(0xffffffffu, rm0, off));
            rm1 = fmaxf(rm1, __shfl_xor_sync(0xffffffffu, rm1, off));
        }
        float mn0 = fmaxf(m0r, rm0), mn1 = fmaxf(m1r, rm1);
        float sc0 = __expf(m0r - mn0), sc1 = __expf(m1r - mn1);
        m0r = mn0; m1r = mn1;
        float rs0 = 0.f, rs1 = 0.f;
#pragma unroll
        for (int ni = 0; ni < 8; ni++) {
            float p0 = __expf(s[ni][0] - mn0);
            float p1 = __expf(s[ni][1] - mn0);
            float p2 = __expf(s[ni][2] - mn1);
            float p3 = __expf(s[ni][3] - mn1);
            rs0 += p0 + p1; rs1 += p2 + p3;
            *(uint2*)&sma[AP + (w * 16 + g) * AT_LDA + ni * 8 + 2 * t] =
                make_uint2(f2tf(p0), f2tf(p1));
            *(uint2*)&sma[AP + (w * 16 + g + 8) * AT_LDA + ni * 8 + 2 * t] =
                make_uint2(f2tf(p2), f2tf(p3));
        }
#pragma unroll
        for (int off = 1; off <= 2; off <<= 1) {
            rs0 += __shfl_xor_sync(0xffffffffu, rs0, off);
            rs1 += __shfl_xor_sync(0xffffffffu, rs1, off);
        }
        l0 = l0 * sc0 + rs0;
        l1 = l1 * sc1 + rs1;
#pragma unroll
        for (int ni = 0; ni < 8; ni++) {
            O[ni][0] *= sc0; O[ni][1] *= sc0;
            O[ni][2] *= sc1; O[ni][3] *= sc1;
        }
        __syncwarp();

        // O += P @ V : A = P (warp strip), B = Vt
        uint32_t aP[8][4];
#pragma unroll
        for (int k = 0; k < 8; k++) {
            uint32_t r0, r1, r2, r3;
            ldsm4(sbase + (uint32_t)(AP + (w * 16 + rowOffA) * AT_LDA) * 4 + k * 32 + byteA,
                  r0, r1, r2, r3);
            aP[k][0] = r0; aP[k][1] = r2; aP[k][2] = r1; aP[k][3] = r3;
        }
#pragma unroll
        for (int ni = 0; ni < 8; ni++) {
            uint32_t bv[4][4];
#pragma unroll
            for (int ch = 0; ch < 4; ch++)
                ldsm4(sbase + (uint32_t)(AV + (ni * 8 + rowOffB) * AT_LDA) * 4 + ch * 64 + byteB,
                      bv[ch][0], bv[ch][1], bv[ch][2], bv[ch][3]);
#pragma unroll
            for (int k = 0; k < 8; k++)
                mma8(O[ni], aP[k][0], aP[k][1], aP[k][2], aP[k][3],
                     bv[k >> 1][(k & 1) * 2], bv[k >> 1][(k & 1) * 2 + 1]);
        }
    }

    float i0 = 1.f / l0, i1 = 1.f / l1;
    float* o0 = out + (size_t)(b * S_ + q0 + w * 16 + g) * 1024 + h * 64;
    float* o1 = out + (size_t)(b * S_ + q0 + w * 16 + g + 8) * 1024 + h * 64;
#pragma unroll
    for (int ni = 0; ni < 8; ni++) {
        *(float2*)(o0 + ni * 8 + 2 * t) = make_float2(O[ni][0] * i0, O[ni][1] * i0);
        *(float2*)(o1 + ni * 8 + 2 * t) = make_float2(O[ni][2] * i1, O[ni][3] * i1);
    }
}

// ---------------------------------------------------------------------------
extern "C" void kernel_launch(void* const* d_in, const int* in_sizes, int n_in,
                              void* d_out, int out_size) {
    const float* hs    = (const float*)d_in[0];
    const float* mask  = (const float*)d_in[1];
    const float* cosb  = (const float*)d_in[2];
    const float* sinb  = (const float*)d_in[3];
    const int*   amask = (const int*)d_in[4];
    const float* W     = (const float*)d_in[5];
    const float* bias  = (const float*)d_in[6];
    const float* loraA = (const float*)d_in[7];
    const float* loraB = (const float*)d_in[8];
    float* out = (float*)d_out;
    (void)in_sizes; (void)n_in; (void)out_size;

    const int GEMM_SMEM = 4 * GM_BUF * 4;    // 73728 bytes
    const int ATTN_SMEM = AT_WORDS * 4;      // 104704 bytes
    cudaFuncSetAttribute(qkv_gemm_tc,
                         cudaFuncAttributeMaxDynamicSharedMemorySize, GEMM_SMEM);
    cudaFuncSetAttribute(attn_tc,
                         cudaFuncAttributeMaxDynamicSharedMemorySize, ATTN_SMEM);

    lora_lo_kernel<<<B_ * S_, 128>>>(hs, loraA, amask);

    dim3 g2(O3_ / 128, (B_ * S_) / 128);
    qkv_gemm_tc<<<g2, 256, GEMM_SMEM>>>(hs, W, bias, loraB, amask);

    rope_kernel<<<(B_ * S_ * 2 * H_ * 32) / 256, 256>>>(cosb, sinb);

    dim3 gt(S_ / 32, 2, B_ * H_);
    vtrans_kernel<<<gt, 256>>>();

    dim3 g4(S_ / 128, H_, B_);
    attn_tc<<<g4, 256, ATTN_SMEM>>>(mask, out);
}

// round 5
// speedup vs baseline: 12.4886x; 1.8503x over previous
#include <cuda_runtime.h>
#include <cuda_fp16.h>
#include <math.h>
#include <stdint.h>

#define B_  8
#define S_  1024
#define D_  1024
#define H_  16
#define O3_ 3072

__device__ float  g_qkv[(size_t)B_ * S_ * O3_];
__device__ float  g_lo[(size_t)B_ * S_ * 4];
__device__ __half g_qh[(size_t)B_ * H_ * S_ * 64];   // roped q, head-major, *0.125
__device__ __half g_kh[(size_t)B_ * H_ * S_ * 64];   // roped k, head-major
__device__ __half g_vt[(size_t)B_ * H_ * 64 * S_];   // v transposed [bh][d][s]

// ---------------------------------------------------------------------------
__device__ __forceinline__ void ldsm4(uint32_t addr, uint32_t& r0, uint32_t& r1,
                                      uint32_t& r2, uint32_t& r3) {
    asm volatile("ldmatrix.sync.aligned.m8n8.x4.shared.b16 {%0,%1,%2,%3}, [%4];"
                 : "=r"(r0), "=r"(r1), "=r"(r2), "=r"(r3) : "r"(addr));
}
__device__ __forceinline__ void mma16(float c[4], uint32_t a0, uint32_t a1,
                                      uint32_t a2, uint32_t a3,
                                      uint32_t b0, uint32_t b1) {
    asm volatile(
        "mma.sync.aligned.m16n8k16.row.col.f32.f16.f16.f32 "
        "{%0,%1,%2,%3},{%4,%5,%6,%7},{%8,%9},{%0,%1,%2,%3};"
        : "+f"(c[0]), "+f"(c[1]), "+f"(c[2]), "+f"(c[3])
        : "r"(a0), "r"(a1), "r"(a2), "r"(a3), "r"(b0), "r"(b1));
}
__device__ __forceinline__ uint32_t h2u(float a, float b) {
    __half2 h = __floats2half2_rn(a, b);
    return *reinterpret_cast<uint32_t*>(&h);
}

// ---------------------------------------------------------------------------
// Kernel 1: lo[b,s,r] = sum_d hs[b,s,d] * lora_A[adapter[b], r, d]   (fp32)
// ---------------------------------------------------------------------------
__global__ void lora_lo_kernel(const float* __restrict__ hs,
                               const float* __restrict__ loraA,
                               const int*   __restrict__ amask) {
    int ms = blockIdx.x;
    int b  = ms >> 10;
    int a  = amask[b];
    const float* hrow = hs    + (size_t)ms * D_;
    const float* Arow = loraA + (size_t)a * 4 * D_;
    float acc[4] = {0.f, 0.f, 0.f, 0.f};
    for (int d = threadIdx.x * 4; d < D_; d += 128 * 4) {
        float4 hv = *(const float4*)(hrow + d);
#pragma unroll
        for (int r = 0; r < 4; r++) {
            float4 av = *(const float4*)(Arow + r * D_ + d);
            acc[r] += hv.x * av.x + hv.y * av.y + hv.z * av.z + hv.w * av.w;
        }
    }
#pragma unroll
    for (int r = 0; r < 4; r++)
#pragma unroll
        for (int off = 16; off; off >>= 1)
            acc[r] += __shfl_xor_sync(0xffffffffu, acc[r], off);
    __shared__ float red[4][4];
    int w = threadIdx.x >> 5, lane = threadIdx.x & 31;
    if (lane == 0) {
#pragma unroll
        for (int r = 0; r < 4; r++) red[w][r] = acc[r];
    }
    __syncthreads();
    if (threadIdx.x < 4) {
        int r = threadIdx.x;
        g_lo[(size_t)ms * 4 + r] = red[0][r] + red[1][r] + red[2][r] + red[3][r];
    }
}

// ---------------------------------------------------------------------------
// Kernel 2: QKV GEMM, fp16 mma m16n8k16 (fp32 accum). Block 128x128, BK=32,
// 8 warps (2x4), warp tile 64x32. Double-buffered half smem, stride 40.
// ---------------------------------------------------------------------------
#define GLDH 40
#define GBUF 5120   // 128*40 halfs per buffer

__global__ __launch_bounds__(256) void qkv_gemm_tc(
        const float* __restrict__ hs, const float* __restrict__ W,
        const float* __restrict__ bias, const float* __restrict__ loraB,
        const int* __restrict__ amask) {
    extern __shared__ __half smg[];     // As[2][GBUF], Bs[2][GBUF]
    const int tid  = threadIdx.x;
    const int lane = tid & 31, wid = tid >> 5;
    const int wm = wid & 1, wn = wid >> 1;
    const int m0 = blockIdx.y * 128, n0 = blockIdx.x * 128;

    uint32_t sb = (uint32_t)__cvta_generic_to_shared(smg);

    const int srow = tid >> 3;          // 0..31
    const int sc4  = (tid & 7) * 4;     // 0..28

    const float* gA = hs + (size_t)m0 * D_;
    const float* gB = W  + (size_t)n0 * D_;

    float4 ar[4], br[4];
#pragma unroll
    for (int i = 0; i < 4; i++) {
        ar[i] = *(const float4*)(gA + (size_t)(srow + i * 32) * D_ + sc4);
        br[i] = *(const float4*)(gB + (size_t)(srow + i * 32) * D_ + sc4);
    }
#pragma unroll
    for (int i = 0; i < 4; i++) {
        int r = srow + i * 32;
        *(uint2*)&smg[r * GLDH + sc4] =
            make_uint2(h2u(ar[i].x, ar[i].y), h2u(ar[i].z, ar[i].w));
        *(uint2*)&smg[2 * GBUF + r * GLDH + sc4] =
            make_uint2(h2u(br[i].x, br[i].y), h2u(br[i].z, br[i].w));
    }
    __syncthreads();

    float acc[4][4][4];
#pragma unroll
    for (int mi = 0; mi < 4; mi++)
#pragma unroll
        for (int ni = 0; ni < 4; ni++)
#pragma unroll
            for (int c = 0; c < 4; c++) acc[mi][ni][c] = 0.f;

    const int rowA = lane & 15;
    const int kA   = (lane >> 4) * 8;
    const int rowB = (lane & 7) + ((lane >> 4) & 1) * 8;
    const int kB   = ((lane >> 3) & 1) * 8;

    const int NKS = D_ / 32;
    for (int ks = 0; ks < NKS; ks++) {
        int buf = ks & 1;
        if (ks + 1 < NKS) {
#pragma unroll
            for (int i = 0; i < 4; i++) {
                ar[i] = *(const float4*)(gA + (size_t)(srow + i * 32) * D_ + (ks + 1) * 32 + sc4);
                br[i] = *(const float4*)(gB + (size_t)(srow + i * 32) * D_ + (ks + 1) * 32 + sc4);
            }
        }
        uint32_t abase = sb + (uint32_t)(buf * GBUF) * 2;
        uint32_t bbase = sb + (uint32_t)(2 * GBUF + buf * GBUF) * 2;
#pragma unroll
        for (int kt = 0; kt < 2; kt++) {
            uint32_t a[4][4];
#pragma unroll
            for (int mi = 0; mi < 4; mi++)
                ldsm4(abase + (uint32_t)((wm * 64 + mi * 16 + rowA) * GLDH + kt * 16 + kA) * 2,
                      a[mi][0], a[mi][1], a[mi][2], a[mi][3]);
#pragma unroll
            for (int np = 0; np < 2; np++) {
                uint32_t b0, b1, b2, b3;
                ldsm4(bbase + (uint32_t)((wn * 32 + np * 16 + rowB) * GLDH + kt * 16 + kB) * 2,
                      b0, b1, b2, b3);
#pragma unroll
                for (int mi = 0; mi < 4; mi++) {
                    mma16(acc[mi][np * 2],     a[mi][0], a[mi][1], a[mi][2], a[mi][3], b0, b1);
                    mma16(acc[mi][np * 2 + 1], a[mi][0], a[mi][1], a[mi][2], a[mi][3], b2, b3);
                }
            }
        }
        if (ks + 1 < NKS) {
            int nb = buf ^ 1;
            __syncthreads();
#pragma unroll
            for (int i = 0; i < 4; i++) {
                int r = srow + i * 32;
                *(uint2*)&smg[nb * GBUF + r * GLDH + sc4] =
                    make_uint2(h2u(ar[i].x, ar[i].y), h2u(ar[i].z, ar[i].w));
                *(uint2*)&smg[2 * GBUF + nb * GBUF + r * GLDH + sc4] =
                    make_uint2(h2u(br[i].x, br[i].y), h2u(br[i].z, br[i].w));
            }
            __syncthreads();
        }
    }

    // epilogue: bias + 0.25 * lo·loraB (fp32)
    const int g = lane >> 2, t = lane & 3;
    int aidx = amask[m0 >> 10];
    float4 loa[4], lob[4];
#pragma unroll
    for (int mi = 0; mi < 4; mi++) {
        int ra = m0 + wm * 64 + mi * 16 + g;
        loa[mi] = *(const float4*)&g_lo[(size_t)ra * 4];
        lob[mi] = *(const float4*)&g_lo[(size_t)(ra + 8) * 4];
    }
#pragma unroll
    for (int ni = 0; ni < 4; ni++) {
        int col = n0 + wn * 32 + ni * 8 + 2 * t;
        float4 LB0 = *(const float4*)&loraB[((size_t)aidx * O3_ + col) * 4];
        float4 LB1 = *(const float4*)&loraB[((size_t)aidx * O3_ + col + 1) * 4];
        float bs0 = bias[col], bs1 = bias[col + 1];
#pragma unroll
        for (int mi = 0; mi < 4; mi++) {
            int ra = m0 + wm * 64 + mi * 16 + g;
            float d00 = acc[mi][ni][0] + bs0 +
                0.25f * (loa[mi].x * LB0.x + loa[mi].y * LB0.y + loa[mi].z * LB0.z + loa[mi].w * LB0.w);
            float d01 = acc[mi][ni][1] + bs1 +
                0.25f * (loa[mi].x * LB1.x + loa[mi].y * LB1.y + loa[mi].z * LB1.z + loa[mi].w * LB1.w);
            float d10 = acc[mi][ni][2] + bs0 +
                0.25f * (lob[mi].x * LB0.x + lob[mi].y * LB0.y + lob[mi].z * LB0.z + lob[mi].w * LB0.w);
            float d11 = acc[mi][ni][3] + bs1 +
                0.25f * (lob[mi].x * LB1.x + lob[mi].y * LB1.y + lob[mi].z * LB1.z + lob[mi].w * LB1.w);
            *(float2*)&g_qkv[(size_t)ra * O3_ + col]       = make_float2(d00, d01);
            *(float2*)&g_qkv[(size_t)(ra + 8) * O3_ + col] = make_float2(d10, d11);
        }
    }
}

// ---------------------------------------------------------------------------
// Kernel 3: RoPE q,k -> head-major half buffers (q scaled by 0.125)
// ---------------------------------------------------------------------------
__global__ void rope_kernel(const float* __restrict__ cosb,
                            const float* __restrict__ sinb) {
    int idx = blockIdx.x * blockDim.x + threadIdx.x;   // B*S*2*H*32
    int i  = idx & 31;
    int hh = (idx >> 5) & 15;
    int t  = (idx >> 9) & 1;
    int bs = idx >> 10;
    int b  = bs >> 10, s = bs & 1023;
    size_t base = ((size_t)bs * 3 + t) * 1024 + hh * 64;
    float x1 = g_qkv[base + i], x2 = g_qkv[base + i + 32];
    size_t cb = (size_t)bs * 64;
    float c1 = cosb[cb + i], c2 = cosb[cb + i + 32];
    float s1 = sinb[cb + i], s2 = sinb[cb + i + 32];
    float n1 = x1 * c1 - x2 * s1;
    float n2 = x2 * c2 + x1 * s2;
    size_t o = ((size_t)(b * H_ + hh) * S_ + s) * 64;
    if (t == 0) {
        g_qh[o + i]      = __float2half(n1 * 0.125f);
        g_qh[o + i + 32] = __float2half(n2 * 0.125f);
    } else {
        g_kh[o + i]      = __float2half(n1);
        g_kh[o + i + 32] = __float2half(n2);
    }
}

// ---------------------------------------------------------------------------
// Kernel 3b: V transpose -> g_vt[bh][d][s] (half)
// ---------------------------------------------------------------------------
__global__ void vtrans_kernel() {
    __shared__ float t[32][33];
    int b  = blockIdx.z >> 4, hh = blockIdx.z & 15;
    int s0 = blockIdx.x * 32, d0 = blockIdx.y * 32;
    int tx = threadIdx.x & 31, ty = threadIdx.x >> 5;
#pragma unroll
    for (int i = 0; i < 4; i++) {
        int s = ty + i * 8;
        t[s][tx] = g_qkv[((size_t)(b * S_ + s0 + s) * 3 + 2) * 1024 + hh * 64 + d0 + tx];
    }
    __syncthreads();
#pragma unroll
    for (int i = 0; i < 4; i++) {
        int d = ty + i * 8;
        g_vt[((size_t)(b * H_ + hh) * 64 + d0 + d) * S_ + s0 + tx] = __float2half(t[tx][d]);
    }
}

// ---------------------------------------------------------------------------
// Kernel 4: flash attention, fp16 mma m16n8k16. Block = 128 q rows, 8 warps.
// Smem halfs (stride 72): Q[128][72], K[64][72], Vt[64][72], P[128][72]; mask f32[64]
// ---------------------------------------------------------------------------
#define ALDH 72
#define HQ 0
#define HK 9216
#define HV 13824
#define HP 18432
#define AT_HALFS 27648

__global__ __launch_bounds__(256, 2) void attn_tc(const float* __restrict__ mask,
                                                  float* __restrict__ out) {
    extern __shared__ __half smh[];
    float* msk = (float*)(smh + AT_HALFS);
    const int tid = threadIdx.x;
    const int lane = tid & 31, w = tid >> 5;
    const int q0 = blockIdx.x * 128;
    const int hh = blockIdx.y;
    const int b  = blockIdx.z;
    const int bh = b * H_ + hh;
    const int g = lane >> 2, t = lane & 3;

    uint32_t sb = (uint32_t)__cvta_generic_to_shared(smh);
    const int rowA = lane & 15;
    const int kA   = (lane >> 4) * 8;
    const int rowB = (lane & 7) + ((lane >> 4) & 1) * 8;
    const int kB   = ((lane >> 3) & 1) * 8;

    // Load Q tile (128 x 64 halfs)
    for (int idx = tid * 8; idx < 128 * 64; idx += 2048) {
        int r = idx >> 6, c = idx & 63;
        *(uint4*)&smh[HQ + r * ALDH + c] =
            *(const uint4*)&g_qh[((size_t)bh * S_ + q0 + r) * 64 + c];
    }
    __syncthreads();

    // Cache Q fragments: 4 k-steps (k16 each)
    uint32_t aQ[4][4];
#pragma unroll
    for (int kt = 0; kt < 4; kt++)
        ldsm4(sb + (uint32_t)(HQ + (w * 16 + rowA) * ALDH + kt * 16 + kA) * 2,
              aQ[kt][0], aQ[kt][1], aQ[kt][2], aQ[kt][3]);

    float O[8][4];
#pragma unroll
    for (int ni = 0; ni < 8; ni++)
#pragma unroll
        for (int c = 0; c < 4; c++) O[ni][c] = 0.f;
    float m0r = -1e30f, m1r = -1e30f, l0 = 0.f, l1 = 0.f;

    for (int k0 = 0; k0 < S_; k0 += 64) {
        __syncthreads();
        for (int idx = tid * 8; idx < 64 * 64; idx += 2048) {
            int r = idx >> 6, c = idx & 63;
            *(uint4*)&smh[HK + r * ALDH + c] =
                *(const uint4*)&g_kh[((size_t)bh * S_ + k0 + r) * 64 + c];
            *(uint4*)&smh[HV + r * ALDH + c] =
                *(const uint4*)&g_vt[((size_t)bh * 64 + r) * S_ + k0 + c];
        }
        if (tid < 64) msk[tid] = mask[(size_t)b * S_ + k0 + tid];
        __syncthreads();

        // S = Q K^T
        float s[8][4];
#pragma unroll
        for (int ni = 0; ni < 8; ni++)
            s[ni][0] = s[ni][1] = s[ni][2] = s[ni][3] = 0.f;
#pragma unroll
        for (int np = 0; np < 4; np++)
#pragma unroll
            for (int kt = 0; kt < 4; kt++) {
                uint32_t b0, b1, b2, b3;
                ldsm4(sb + (uint32_t)(HK + (np * 16 + rowB) * ALDH + kt * 16 + kB) * 2,
                      b0, b1, b2, b3);
                mma16(s[np * 2],     aQ[kt][0], aQ[kt][1], aQ[kt][2], aQ[kt][3], b0, b1);
                mma16(s[np * 2 + 1], aQ[kt][0], aQ[kt][1], aQ[kt][2], aQ[kt][3], b2, b3);
            }

        // mask + online softmax (rows g, g+8 of warp strip)
        float rm0 = -1e30f, rm1 = -1e30f;
#pragma unroll
        for (int ni = 0; ni < 8; ni++) {
            float mk0 = msk[ni * 8 + 2 * t];
            float mk1 = msk[ni * 8 + 2 * t + 1];
            s[ni][0] += mk0; s[ni][1] += mk1;
            s[ni][2] += mk0; s[ni][3] += mk1;
            rm0 = fmaxf(rm0, fmaxf(s[ni][0], s[ni][1]));
            rm1 = fmaxf(rm1, fmaxf(s[ni][2], s[ni][3]));
        }
#pragma unroll
        for (int off = 1; off <= 2; off <<= 1) {
            rm0 = fmaxf(rm0, __shfl_xor_sync(0xffffffffu, rm0, off));
            rm1 = fmaxf(rm1, __shfl_xor_sync(0xffffffffu, rm1, off));
        }
        float mn0 = fmaxf(m0r, rm0), mn1 = fmaxf(m1r, rm1);
        float sc0 = __expf(m0r - mn0), sc1 = __expf(m1r - mn1);
        m0r = mn0; m1r = mn1;
        float rs0 = 0.f, rs1 = 0.f;
#pragma unroll
        for (int ni = 0; ni < 8; ni++) {
            float p0 = __expf(s[ni][0] - mn0);
            float p1 = __expf(s[ni][1] - mn0);
            float p2 = __expf(s[ni][2] - mn1);
            float p3 = __expf(s[ni][3] - mn1);
            rs0 += p0 + p1; rs1 += p2 + p3;
            *(uint32_t*)&smh[HP + (w * 16 + g) * ALDH + ni * 8 + 2 * t]     = h2u(p0, p1);
            *(uint32_t*)&smh[HP + (w * 16 + g + 8) * ALDH + ni * 8 + 2 * t] = h2u(p2, p3);
        }
#pragma unroll
        for (int off = 1; off <= 2; off <<= 1) {
            rs0 += __shfl_xor_sync(0xffffffffu, rs0, off);
            rs1 += __shfl_xor_sync(0xffffffffu, rs1, off);
        }
        l0 = l0 * sc0 + rs0;
        l1 = l1 * sc1 + rs1;
#pragma unroll
        for (int ni = 0; ni < 8; ni++) {
            O[ni][0] *= sc0; O[ni][1] *= sc0;
            O[ni][2] *= sc1; O[ni][3] *= sc1;
        }
        __syncwarp();

        // O += P @ V
        uint32_t aP[4][4];
#pragma unroll
        for (int kt = 0; kt < 4; kt++)
            ldsm4(sb + (uint32_t)(HP + (w * 16 + rowA) * ALDH + kt * 16 + kA) * 2,
                  aP[kt][0], aP[kt][1], aP[kt][2], aP[kt][3]);
#pragma unroll
        for (int np = 0; np < 4; np++)
#pragma unroll
            for (int kt = 0; kt < 4; kt++) {
                uint32_t b0, b1, b2, b3;
                ldsm4(sb + (uint32_t)(HV + (np * 16 + rowB) * ALDH + kt * 16 + kB) * 2,
                      b0, b1, b2, b3);
                mma16(O[np * 2],     aP[kt][0], aP[kt][1], aP[kt][2], aP[kt][3], b0, b1);
                mma16(O[np * 2 + 1], aP[kt][0], aP[kt][1], aP[kt][2], aP[kt][3], b2, b3);
            }
    }

    float i0 = 1.f / l0, i1 = 1.f / l1;
    float* o0 = out + (size_t)(b * S_ + q0 + w * 16 + g) * 1024 + hh * 64;
    float* o1 = out + (size_t)(b * S_ + q0 + w * 16 + g + 8) * 1024 + hh * 64;
#pragma unroll
    for (int ni = 0; ni < 8; ni++) {
        *(float2*)(o0 + ni * 8 + 2 * t) = make_float2(O[ni][0] * i0, O[ni][1] * i0);
        *(float2*)(o1 + ni * 8 + 2 * t) = make_float2(O[ni][2] * i1, O[ni][3] * i1);
    }
}

// ---------------------------------------------------------------------------
extern "C" void kernel_launch(void* const* d_in, const int* in_sizes, int n_in,
                              void* d_out, int out_size) {
    const float* hs    = (const float*)d_in[0];
    const float* mask  = (const float*)d_in[1];
    const float* cosb  = (const float*)d_in[2];
    const float* sinb  = (const float*)d_in[3];
    const int*   amask = (const int*)d_in[4];
    const float* W     = (const float*)d_in[5];
    const float* bias  = (const float*)d_in[6];
    const float* loraA = (const float*)d_in[7];
    const float* loraB = (const float*)d_in[8];
    float* out = (float*)d_out;
    (void)in_sizes; (void)n_in; (void)out_size;

    const int GEMM_SMEM = 4 * GBUF * 2;             // 40960 bytes
    const int ATTN_SMEM = AT_HALFS * 2 + 64 * 4;    // 55552 bytes
    cudaFuncSetAttribute(qkv_gemm_tc,
                         cudaFuncAttributeMaxDynamicSharedMemorySize, GEMM_SMEM);
    cudaFuncSetAttribute(attn_tc,
                         cudaFuncAttributeMaxDynamicSharedMemorySize, ATTN_SMEM);

    lora_lo_kernel<<<B_ * S_, 128>>>(hs, loraA, amask);

    dim3 g2(O3_ / 128, (B_ * S_) / 128);
    qkv_gemm_tc<<<g2, 256, GEMM_SMEM>>>(hs, W, bias, loraB, amask);

    rope_kernel<<<(B_ * S_ * 2 * H_ * 32) / 256, 256>>>(cosb, sinb);

    dim3 gt(S_ / 32, 2, B_ * H_);
    vtrans_kernel<<<gt, 256>>>();

    dim3 g4(S_ / 128, H_, B_);
    attn_tc<<<g4, 256, ATTN_SMEM>>>(mask, out);
}